// round 13
// baseline (speedup 1.0000x reference)
#include <cuda_runtime.h>
#include <cuda_bf16.h>
#include <stdint.h>

// ---------------------------------------------------------------------------
// out[b,i,j] = (x_i - x_j)^T M_b (x_i - x_j) = q_i + q_j - 2*G[b,i,j]
//   G = x M_b x^T (symmetric),  q_i = G_ii.   B=16, N=D=256, fp32.
// Split-bf16 (hi/lo) mma.sync GEMMs, fp32 accum. M symmetric => no transposes.
// R13 (= R12 resubmit after infra failure): TWO launches total.
//  gemm1: A = raw f32 x, B = raw f32 M; both inline-converted to swizzled
//         bf16 h/l one chunk AHEAD of use (raw ring 3-deep, bf16 ring 2-deep,
//         same-thread-bytes). b==0 blocks publish split-x to g_Xh/g_Xl.
//         Epilogue: Yh/Yl + q partials (g_qp, no atomics, no zero-init).
//  gemm2: R7 config — 4-stage 16KB pre-split pipeline, full 256-block grid;
//         qs[row] = sum of 16 partials.
// ---------------------------------------------------------------------------

__device__ __align__(16) unsigned short g_Xh[256 * 256];
__device__ __align__(16) unsigned short g_Xl[256 * 256];
__device__ __align__(16) unsigned short g_Yh[16 * 256 * 256];
__device__ __align__(16) unsigned short g_Yl[16 * 256 * 256];
__device__ float g_qp[16 * 16 * 256];    // [b][bj*4+wn][row]

__device__ __forceinline__ uint32_t smem_u32(const void* p) {
    uint32_t a;
    asm("{ .reg .u64 t; cvta.to.shared.u64 t, %1; cvt.u32.u64 %0, t; }"
        : "=r"(a) : "l"(p));
    return a;
}

__device__ __forceinline__ void cp16(uint32_t dst, const void* src) {
    asm volatile("cp.async.cg.shared.global [%0], [%1], 16;"
                 :: "r"(dst), "l"(src) : "memory");
}
#define CP_COMMIT() asm volatile("cp.async.commit_group;" ::: "memory")
template <int N>
__device__ __forceinline__ void cp_wait() {
    asm volatile("cp.async.wait_group %0;" :: "n"(N) : "memory");
}

__device__ __forceinline__ void ldm_x4(uint32_t* r, uint32_t addr) {
    asm volatile("ldmatrix.sync.aligned.m8n8.x4.shared.b16 {%0,%1,%2,%3}, [%4];"
                 : "=r"(r[0]), "=r"(r[1]), "=r"(r[2]), "=r"(r[3]) : "r"(addr));
}
__device__ __forceinline__ void mma_bf16(float* d, const uint32_t* a,
                                         uint32_t b0, uint32_t b1) {
    asm volatile(
        "mma.sync.aligned.m16n8k16.row.col.f32.bf16.bf16.f32 "
        "{%0,%1,%2,%3}, {%4,%5,%6,%7}, {%8,%9}, {%0,%1,%2,%3};"
        : "+f"(d[0]), "+f"(d[1]), "+f"(d[2]), "+f"(d[3])
        : "r"(a[0]), "r"(a[1]), "r"(a[2]), "r"(a[3]), "r"(b0), "r"(b1));
}

__device__ __forceinline__ void split_pack(float v0, float v1,
                                           uint32_t& ph, uint32_t& pl) {
    const __nv_bfloat16 h0 = __float2bfloat16(v0);
    const __nv_bfloat16 h1 = __float2bfloat16(v1);
    const __nv_bfloat16 e0 = __float2bfloat16(v0 - __bfloat162float(h0));
    const __nv_bfloat16 e1 = __float2bfloat16(v1 - __bfloat162float(h1));
    ph = (uint32_t)__bfloat16_as_ushort(h0) | ((uint32_t)__bfloat16_as_ushort(h1) << 16);
    pl = (uint32_t)__bfloat16_as_ushort(e0) | ((uint32_t)__bfloat16_as_ushort(e1) << 16);
}

// ---------------------------------------------------------------------------
// gemm1 smem layout:
//   bf16 ring (2 slots x 16384): slot s2 @ s2*16384:
//     Ah@+0 (64x32 bf16, 64B rows, 16B-chunk swizzle), Al@+4096,
//     Bh@+8192, Bl@+12288
//   raw ring  (3 slots x 18432) @ 32768: slot s3:
//     Af32@+0 (64 rows x 144B stride), Bf32@+9216 (same)
// ---------------------------------------------------------------------------
#define BF16_SLOT 16384
#define RAW_SLOT  18432
#define RAW_BASE  32768
#define SMEM_B1   (RAW_BASE + 3 * RAW_SLOT)          // 88064

#define STG2     16384
#define SMEM_B2  (4 * STG2 + 1024)

// ------------------------------ PHASE 1 ------------------------------------
__global__ void __launch_bounds__(256) k_gemm1(const float* __restrict__ x,
                                               const float* __restrict__ M) {
    extern __shared__ __align__(128) unsigned char smem[];
    const uint32_t sb = smem_u32(smem);
    const int tid = threadIdx.x;
    const int wid = tid >> 5, l = tid & 31;
    const int wm  = wid & 1, wn = wid >> 1;      // 2 x 4 warp grid
    const int b   = blockIdx.z;
    const int bj  = blockIdx.x;
    const int bm0 = blockIdx.y * 64;
    const int bn0 = bj * 64;

    const float* AX = x + bm0 * 256;
    const float* BM = M + (size_t)b * 65536 + bn0 * 256;

    // raw f32 chunk kc -> raw slot kc%3 (A rows of x, B rows of M)
    auto issue = [&](int kc) {
        const uint32_t rs = sb + RAW_BASE + (kc % 3) * RAW_SLOT;
        const int k0 = kc * 32;
        const int row = tid >> 2;
        const int c = tid & 3;
        const uint32_t da = rs + row * 144 + c * 32;
        const float* sa = AX + row * 256 + k0 + c * 8;
        cp16(da,      sa);
        cp16(da + 16, sa + 4);
        const uint32_t db = rs + 9216 + row * 144 + c * 32;
        const float* sbp = BM + row * 256 + k0 + c * 8;
        cp16(db,      sbp);
        cp16(db + 16, sbp + 4);
    };

    // convert chunk cc: raw slot cc%3 -> bf16 slot cc&1 (same-thread bytes)
    auto convert = [&](int cc) {
        const uint32_t rs = sb + RAW_BASE + (cc % 3) * RAW_SLOT;
        const uint32_t ds = sb + (cc & 1) * BF16_SLOT;
        const int r  = tid >> 2;
        const int kh = tid & 3;
        const uint32_t sw = r * 64 + ((kh ^ ((r >> 1) & 3)) << 4);

        // A (x rows)
        {
            const uint32_t ra = rs + r * 144 + kh * 32;
            float4 f0, f1;
            asm volatile("ld.shared.v4.f32 {%0,%1,%2,%3}, [%4];"
                         : "=f"(f0.x), "=f"(f0.y), "=f"(f0.z), "=f"(f0.w) : "r"(ra));
            asm volatile("ld.shared.v4.f32 {%0,%1,%2,%3}, [%4];"
                         : "=f"(f1.x), "=f"(f1.y), "=f"(f1.z), "=f"(f1.w) : "r"(ra + 16));
            uint32_t ph[4], pl[4];
            split_pack(f0.x, f0.y, ph[0], pl[0]);
            split_pack(f0.z, f0.w, ph[1], pl[1]);
            split_pack(f1.x, f1.y, ph[2], pl[2]);
            split_pack(f1.z, f1.w, ph[3], pl[3]);
            uint4 vh = make_uint4(ph[0], ph[1], ph[2], ph[3]);
            uint4 vl = make_uint4(pl[0], pl[1], pl[2], pl[3]);
            asm volatile("st.shared.v4.b32 [%0], {%1,%2,%3,%4};"
                         :: "r"(ds + sw), "r"(vh.x), "r"(vh.y), "r"(vh.z), "r"(vh.w));
            asm volatile("st.shared.v4.b32 [%0], {%1,%2,%3,%4};"
                         :: "r"(ds + 4096 + sw), "r"(vl.x), "r"(vl.y), "r"(vl.z), "r"(vl.w));
            if (b == 0) {   // publish split-x for gemm2 (duplicates benign)
                const int gi = (bm0 + r) * 256 + cc * 32 + kh * 8;
                *(uint4*)(g_Xh + gi) = vh;
                *(uint4*)(g_Xl + gi) = vl;
            }
        }
        // B (M rows)
        {
            const uint32_t rb = rs + 9216 + r * 144 + kh * 32;
            float4 f0, f1;
            asm volatile("ld.shared.v4.f32 {%0,%1,%2,%3}, [%4];"
                         : "=f"(f0.x), "=f"(f0.y), "=f"(f0.z), "=f"(f0.w) : "r"(rb));
            asm volatile("ld.shared.v4.f32 {%0,%1,%2,%3}, [%4];"
                         : "=f"(f1.x), "=f"(f1.y), "=f"(f1.z), "=f"(f1.w) : "r"(rb + 16));
            uint32_t ph[4], pl[4];
            split_pack(f0.x, f0.y, ph[0], pl[0]);
            split_pack(f0.z, f0.w, ph[1], pl[1]);
            split_pack(f1.x, f1.y, ph[2], pl[2]);
            split_pack(f1.z, f1.w, ph[3], pl[3]);
            asm volatile("st.shared.v4.b32 [%0], {%1,%2,%3,%4};"
                         :: "r"(ds + 8192 + sw), "r"(ph[0]), "r"(ph[1]), "r"(ph[2]), "r"(ph[3]));
            asm volatile("st.shared.v4.b32 [%0], {%1,%2,%3,%4};"
                         :: "r"(ds + 12288 + sw), "r"(pl[0]), "r"(pl[1]), "r"(pl[2]), "r"(pl[3]));
        }
    };

    float acc[2][2][4] = {};   // [mt][n8 j][reg]

    issue(0); CP_COMMIT();
    issue(1); CP_COMMIT();
    issue(2); CP_COMMIT();
    cp_wait<2>();              // chunk 0 raw landed (own bytes visible)
    convert(0);

    const int rA = (l & 15);
    const int hA = (l >> 4);
    const int rB = ((l >> 4) << 3) + (l & 7);
    const int hB = ((l >> 3) & 1);

    for (int i = 0; i < 8; i++) {
        if (i <= 5) cp_wait<1>();      // chunk i+1 raw landed
        else        cp_wait<0>();
        __syncthreads();               // publishes convert(i); orders raw reuse
        if (i + 3 < 8) { issue(i + 3); CP_COMMIT(); }
        if (i + 1 < 8) convert(i + 1); // overlapped with this iter's mmas

        const uint32_t st = sb + (i & 1) * BF16_SLOT;
        uint32_t ah[2][2][4], al[2][2][4], bh[2][4], bl[2][4];
        #pragma unroll
        for (int ks = 0; ks < 2; ks++) {
            #pragma unroll
            for (int mt = 0; mt < 2; mt++) {
                const int row = wm * 32 + mt * 16 + rA;
                const int c = (ks * 2 + hA) ^ ((row >> 1) & 3);
                const uint32_t a = st + row * 64 + (c << 4);
                ldm_x4(ah[ks][mt], a);
                ldm_x4(al[ks][mt], a + 4096);
            }
            {
                const int row = wn * 16 + rB;
                const int c = (ks * 2 + hB) ^ ((row >> 1) & 3);
                const uint32_t a = st + 8192 + row * 64 + (c << 4);
                ldm_x4(bh[ks], a);
                ldm_x4(bl[ks], a + 4096);
            }
        }
        #pragma unroll
        for (int ks = 0; ks < 2; ks++)
            #pragma unroll
            for (int mt = 0; mt < 2; mt++)
                #pragma unroll
                for (int j = 0; j < 2; j++) {
                    const int o = j * 2;
                    mma_bf16(acc[mt][j], ah[ks][mt], bh[ks][o], bh[ks][o + 1]);
                    mma_bf16(acc[mt][j], ah[ks][mt], bl[ks][o], bl[ks][o + 1]);
                    mma_bf16(acc[mt][j], al[ks][mt], bh[ks][o], bh[ks][o + 1]);
                }
    }

    // epilogue: Y split + q partials (no atomics)
    const int lr = l >> 2;
    const int lc = (l & 3) * 2;
    unsigned short* yh = g_Yh + b * 65536;
    unsigned short* yl = g_Yl + b * 65536;
    float* qp = g_qp + (b * 16 + bj * 4 + wn) * 256;
    #pragma unroll
    for (int mt = 0; mt < 2; mt++)
        #pragma unroll
        for (int half = 0; half < 2; half++) {
            const int row = bm0 + wm * 32 + mt * 16 + lr + half * 8;
            float qpart = 0.0f;
            #pragma unroll
            for (int j = 0; j < 2; j++) {
                const int col = bn0 + wn * 16 + j * 8 + lc;
                const float v0 = acc[mt][j][half * 2 + 0];
                const float v1 = acc[mt][j][half * 2 + 1];
                const float2 xv = *(const float2*)(x + row * 256 + col);
                qpart += v0 * xv.x + v1 * xv.y;
                uint32_t ph, pl;
                split_pack(v0, v1, ph, pl);
                *(uint32_t*)(yh + row * 256 + col) = ph;
                *(uint32_t*)(yl + row * 256 + col) = pl;
            }
            qpart += __shfl_xor_sync(0xffffffffu, qpart, 1);
            qpart += __shfl_xor_sync(0xffffffffu, qpart, 2);
            if ((l & 3) == 0) qp[row] = qpart;
        }
}

// ------------------------------ PHASE 2 ------------------------------------
__global__ void __launch_bounds__(256) k_gemm2(float* __restrict__ out) {
    extern __shared__ __align__(128) unsigned char smem[];
    const uint32_t sb = smem_u32(smem);
    const uint32_t QSO = 4 * (uint32_t)STG2;
    const int tid = threadIdx.x;
    const int wid = tid >> 5, l = tid & 31;
    const int wm  = wid & 1, wn = wid >> 1;
    const int b   = blockIdx.z;
    const int bm0 = blockIdx.y * 64;
    const int bn0 = blockIdx.x * 64;

    const unsigned short* Ah = g_Yh + b * 65536 + bm0 * 256;
    const unsigned short* Al = g_Yl + b * 65536 + bm0 * 256;
    const unsigned short* Bh = g_Xh + bn0 * 256;
    const unsigned short* Bl = g_Xl + bn0 * 256;

    {   // qs[row] = sum of 16 partials
        float* qs = (float*)(smem + QSO);
        float s = 0.0f;
        #pragma unroll
        for (int p = 0; p < 16; p++)
            s += g_qp[(b * 16 + p) * 256 + tid];
        qs[tid] = s;
    }

    auto issue = [&](int kc, int s) {
        const uint32_t st = sb + s * STG2;
        const int k0 = kc * 32;
        const int row = tid >> 2;
        const int c = tid & 3;
        const uint32_t d = st + row * 64 + ((c ^ ((row >> 1) & 3)) << 4);
        const int go = row * 256 + k0 + c * 8;
        cp16(d,         Ah + go);
        cp16(d + 4096,  Al + go);
        cp16(d + 8192,  Bh + go);
        cp16(d + 12288, Bl + go);
    };

    float acc[2][2][4] = {};

    issue(0, 0); CP_COMMIT();
    issue(1, 1); CP_COMMIT();
    issue(2, 2); CP_COMMIT();

    const int rA = (l & 15);
    const int hA = (l >> 4);
    const int rB = ((l >> 4) << 3) + (l & 7);
    const int hB = ((l >> 3) & 1);

    for (int i = 0; i < 8; i++) {
        cp_wait<2>();
        __syncthreads();
        if (i + 3 < 8) issue(i + 3, (i + 3) & 3);
        CP_COMMIT();

        const uint32_t st = sb + (i & 3) * STG2;
        uint32_t ah[2][2][4], al[2][2][4], bh[2][4], bl[2][4];
        #pragma unroll
        for (int ks = 0; ks < 2; ks++) {
            #pragma unroll
            for (int mt = 0; mt < 2; mt++) {
                const int row = wm * 32 + mt * 16 + rA;
                const int c = (ks * 2 + hA) ^ ((row >> 1) & 3);
                const uint32_t a = st + row * 64 + (c << 4);
                ldm_x4(ah[ks][mt], a);
                ldm_x4(al[ks][mt], a + 4096);
            }
            {
                const int row = wn * 16 + rB;
                const int c = (ks * 2 + hB) ^ ((row >> 1) & 3);
                const uint32_t a = st + 8192 + row * 64 + (c << 4);
                ldm_x4(bh[ks], a);
                ldm_x4(bl[ks], a + 4096);
            }
        }
        #pragma unroll
        for (int ks = 0; ks < 2; ks++)
            #pragma unroll
            for (int mt = 0; mt < 2; mt++)
                #pragma unroll
                for (int j = 0; j < 2; j++) {
                    const int o = j * 2;
                    mma_bf16(acc[mt][j], ah[ks][mt], bh[ks][o], bh[ks][o + 1]);
                    mma_bf16(acc[mt][j], ah[ks][mt], bl[ks][o], bl[ks][o + 1]);
                    mma_bf16(acc[mt][j], al[ks][mt], bh[ks][o], bh[ks][o + 1]);
                }
    }

    const int lr = l >> 2;
    const int lc = (l & 3) * 2;
    const float* qs = (const float*)(smem + QSO);
    float* ob = out + ((size_t)b << 16);
    #pragma unroll
    for (int mt = 0; mt < 2; mt++)
        #pragma unroll
        for (int j = 0; j < 2; j++) {
            const int col = bn0 + wn * 16 + j * 8 + lc;
            const float qj0 = qs[col], qj1 = qs[col + 1];
            #pragma unroll
            for (int half = 0; half < 2; half++) {
                const int row = bm0 + wm * 32 + mt * 16 + lr + half * 8;
                const float qi = qs[row];
                float2 v;
                v.x = qi + qj0 - 2.0f * acc[mt][j][half * 2 + 0];
                v.y = qi + qj1 - 2.0f * acc[mt][j][half * 2 + 1];
                *(float2*)(ob + row * 256 + col) = v;
            }
        }
}

// ---------------------------------------------------------------------------
extern "C" void kernel_launch(void* const* d_in, const int* in_sizes, int n_in,
                              void* d_out, int out_size) {
    const float* x = (const float*)d_in[0];   // (256, 256) f32
    const float* M = (const float*)d_in[1];   // (16, 256, 256) f32
    float* out = (float*)d_out;               // (16, 256, 256) f32
    (void)in_sizes; (void)n_in; (void)out_size;

    (void)cudaFuncSetAttribute(k_gemm1, cudaFuncAttributeMaxDynamicSharedMemorySize, SMEM_B1);
    (void)cudaFuncSetAttribute(k_gemm2, cudaFuncAttributeMaxDynamicSharedMemorySize, SMEM_B2);

    k_gemm1<<<dim3(4, 4, 16), 256, SMEM_B1>>>(x, M);
    k_gemm2<<<dim3(4, 4, 16), 256, SMEM_B2>>>(out);
}

// round 14
// speedup vs baseline: 1.0644x; 1.0644x over previous
#include <cuda_runtime.h>
#include <cuda_bf16.h>
#include <stdint.h>

// ---------------------------------------------------------------------------
// out[b,i,j] = (x_i - x_j)^T M_b (x_i - x_j) = q_i + q_j - 2*G[b,i,j]
//   G = x M_b x^T,  q_i = G_ii.   B=16, N=D=256, fp32.
// Split-bf16 (hi/lo) mma.sync GEMMs, fp32 accum. M symmetric => no transposes.
// R14: R7 structure (convert kernel + 2 GEMMs, pre-split operands) but GEMM
//      blocks are 512 threads / 16 warps (4m x 4n, warp tile 16x16) to double
//      resident warps per SM. Per-ks fragment loads keep regs <= 64 so two
//      512-thread blocks co-reside per SM.
// ---------------------------------------------------------------------------

__device__ __align__(16) unsigned short g_Xh[256 * 256];
__device__ __align__(16) unsigned short g_Xl[256 * 256];
__device__ __align__(16) unsigned short g_Mh[16 * 256 * 256];
__device__ __align__(16) unsigned short g_Ml[16 * 256 * 256];
__device__ __align__(16) unsigned short g_Yh[16 * 256 * 256];
__device__ __align__(16) unsigned short g_Yl[16 * 256 * 256];
__device__ float g_q[16 * 256];

__device__ __forceinline__ uint32_t smem_u32(const void* p) {
    uint32_t a;
    asm("{ .reg .u64 t; cvta.to.shared.u64 t, %1; cvt.u32.u64 %0, t; }"
        : "=r"(a) : "l"(p));
    return a;
}

__device__ __forceinline__ void cp16(uint32_t dst, const void* src) {
    asm volatile("cp.async.cg.shared.global [%0], [%1], 16;"
                 :: "r"(dst), "l"(src) : "memory");
}
#define CP_COMMIT() asm volatile("cp.async.commit_group;" ::: "memory")
template <int N>
__device__ __forceinline__ void cp_wait() {
    asm volatile("cp.async.wait_group %0;" :: "n"(N) : "memory");
}

__device__ __forceinline__ void ldm_x4(uint32_t* r, uint32_t addr) {
    asm volatile("ldmatrix.sync.aligned.m8n8.x4.shared.b16 {%0,%1,%2,%3}, [%4];"
                 : "=r"(r[0]), "=r"(r[1]), "=r"(r[2]), "=r"(r[3]) : "r"(addr));
}
__device__ __forceinline__ void mma_bf16(float* d, const uint32_t* a,
                                         uint32_t b0, uint32_t b1) {
    asm volatile(
        "mma.sync.aligned.m16n8k16.row.col.f32.bf16.bf16.f32 "
        "{%0,%1,%2,%3}, {%4,%5,%6,%7}, {%8,%9}, {%0,%1,%2,%3};"
        : "+f"(d[0]), "+f"(d[1]), "+f"(d[2]), "+f"(d[3])
        : "r"(a[0]), "r"(a[1]), "r"(a[2]), "r"(a[3]), "r"(b0), "r"(b1));
}

__device__ __forceinline__ void split_pack(float v0, float v1,
                                           uint32_t& ph, uint32_t& pl) {
    const __nv_bfloat16 h0 = __float2bfloat16(v0);
    const __nv_bfloat16 h1 = __float2bfloat16(v1);
    const __nv_bfloat16 e0 = __float2bfloat16(v0 - __bfloat162float(h0));
    const __nv_bfloat16 e1 = __float2bfloat16(v1 - __bfloat162float(h1));
    ph = (uint32_t)__bfloat16_as_ushort(h0) | ((uint32_t)__bfloat16_as_ushort(h1) << 16);
    pl = (uint32_t)__bfloat16_as_ushort(e0) | ((uint32_t)__bfloat16_as_ushort(e1) << 16);
}

// ---------------------------------------------------------------------------
// Convert: x, M -> row-major bf16 hi/lo splits (16 floats/thread); zeroes g_q.
// ---------------------------------------------------------------------------
__global__ void __launch_bounds__(256) k_convert(const float* __restrict__ x,
                                                 const float* __restrict__ M) {
    const int t = blockIdx.x * 256 + threadIdx.x;
    if (t < 16 * 256) g_q[t] = 0.0f;

    const float* src;
    unsigned short *dh, *dl;
    if (t < 65536) {            // M
        src = M + (size_t)t * 16;
        dh = g_Mh + t * 16;  dl = g_Ml + t * 16;
    } else {                    // x
        const int u = t - 65536;
        src = x + (size_t)u * 16;
        dh = g_Xh + u * 16;  dl = g_Xl + u * 16;
    }

    float4 v[4];
    #pragma unroll
    for (int i = 0; i < 4; i++) v[i] = ((const float4*)src)[i];

    uint32_t ph[8], pl[8];
    #pragma unroll
    for (int i = 0; i < 4; i++) {
        split_pack(v[i].x, v[i].y, ph[i * 2 + 0], pl[i * 2 + 0]);
        split_pack(v[i].z, v[i].w, ph[i * 2 + 1], pl[i * 2 + 1]);
    }
    #pragma unroll
    for (int i = 0; i < 2; i++) {
        ((uint4*)dh)[i] = make_uint4(ph[i*4+0], ph[i*4+1], ph[i*4+2], ph[i*4+3]);
        ((uint4*)dl)[i] = make_uint4(pl[i*4+0], pl[i*4+1], pl[i*4+2], pl[i*4+3]);
    }
}

// ---------------------------------------------------------------------------
// GEMM: block tile 64x64, 512 threads = 16 warps (4 m-warps x 4 n-warps),
// warp tile 16x16, BK=32, 4-stage cp.async pipeline.
//   D += Ah*Bh + Ah*Bl + Al*Bh   (fp32 register accum)
// Stage (16384B): Ah@0 (64 rows x 64B), Al@4096, Bh@8192, Bl@12288.
// 16B-chunk swizzle c ^ ((row>>1)&3) — conflict-free stores + ldmatrix.
// PHASE 1: A=x, Bt=M_b rows; epilogue -> Yh/Yl + fused q (atomics).
// PHASE 2: A=Y_b, Bt=x rows; epilogue -> out = q_i + q_j - 2*acc.
// ---------------------------------------------------------------------------
#define STAGES  4
#define STAGE_B 16384
#define QS_OFF  (STAGES * STAGE_B)
#define SMEM_B  (QS_OFF + 1024)

template <int PHASE>
__global__ void __launch_bounds__(512, 2) k_gemm(const float* __restrict__ x,
                                                 float* __restrict__ out) {
    extern __shared__ __align__(128) unsigned char smem[];
    const uint32_t sb = smem_u32(smem);
    const int tid = threadIdx.x;
    const int wid = tid >> 5, l = tid & 31;
    const int wm  = wid & 3, wn = wid >> 2;      // 4 x 4 warp grid
    const int b   = blockIdx.z;
    const int bm0 = blockIdx.y * 64;
    const int bn0 = blockIdx.x * 64;

    const unsigned short *Ah, *Al, *Bh, *Bl;
    if (PHASE == 1) {
        Ah = g_Xh + bm0 * 256;             Al = g_Xl + bm0 * 256;
        Bh = g_Mh + b * 65536 + bn0 * 256; Bl = g_Ml + b * 65536 + bn0 * 256;
    } else {
        Ah = g_Yh + b * 65536 + bm0 * 256; Al = g_Yl + b * 65536 + bm0 * 256;
        Bh = g_Xh + bn0 * 256;             Bl = g_Xl + bn0 * 256;
    }

    // one BK=32 chunk (kc 0..7) into stage s: 2 cp16 per thread
    auto issue = [&](int kc, int s) {
        const uint32_t st = sb + s * STAGE_B;
        const int k0 = kc * 32;
        if (tid < 256) {           // A tile (h+l)
            const int row = tid >> 2;
            const int c = tid & 3;
            const uint32_t d = st + row * 64 + ((c ^ ((row >> 1) & 3)) << 4);
            const int go = row * 256 + k0 + c * 8;
            cp16(d,        Ah + go);
            cp16(d + 4096, Al + go);
        } else {                   // B tile (h+l)
            const int t2 = tid - 256;
            const int row = t2 >> 2;
            const int c = t2 & 3;
            const uint32_t d = st + 8192 + row * 64 + ((c ^ ((row >> 1) & 3)) << 4);
            const int go = row * 256 + k0 + c * 8;
            cp16(d,        Bh + go);
            cp16(d + 4096, Bl + go);
        }
    };

    float acc[2][4] = {};   // [n8 j][reg]

    issue(0, 0); CP_COMMIT();
    issue(1, 1); CP_COMMIT();
    issue(2, 2); CP_COMMIT();

    if (PHASE == 2 && tid < 256) {   // staged q (published by loop barrier)
        ((float*)(smem + QS_OFF))[tid] = g_q[b * 256 + tid];
    }

    const int rA = (l & 15);                    // A: row within m16 tile
    const int hA = (l >> 4);                    // A: k8-half select
    const int rB = ((l >> 4) << 3) + (l & 7);   // B: n-row within n16 group
    const int hB = ((l >> 3) & 1);              // B: k8-half select

    for (int i = 0; i < 8; i++) {
        cp_wait<2>();
        __syncthreads();
        if (i + 3 < 8) issue(i + 3, (i + 3) & 3);
        CP_COMMIT();

        const uint32_t st = sb + (i & 3) * STAGE_B;
        #pragma unroll
        for (int ks = 0; ks < 2; ks++) {
            uint32_t ah[4], al[4], bh[4], bl[4];
            {
                const int row = wm * 16 + rA;
                const int c = (ks * 2 + hA) ^ ((row >> 1) & 3);
                const uint32_t a = st + row * 64 + (c << 4);
                ldm_x4(ah, a);
                ldm_x4(al, a + 4096);
            }
            {
                const int row = wn * 16 + rB;
                const int c = (ks * 2 + hB) ^ ((row >> 1) & 3);
                const uint32_t a = st + 8192 + row * 64 + (c << 4);
                ldm_x4(bh, a);
                ldm_x4(bl, a + 4096);
            }
            #pragma unroll
            for (int j = 0; j < 2; j++) {
                const int o = j * 2;
                mma_bf16(acc[j], ah, bh[o], bh[o + 1]);
                mma_bf16(acc[j], ah, bl[o], bl[o + 1]);
                mma_bf16(acc[j], al, bh[o], bh[o + 1]);
            }
        }
    }

    // ------------------------------------------------------------------ epi
    const int lr = l >> 2;          // 0..7
    const int lc = (l & 3) * 2;     // 0,2,4,6

    if (PHASE == 1) {
        unsigned short* yh = g_Yh + b * 65536;
        unsigned short* yl = g_Yl + b * 65536;
        #pragma unroll
        for (int half = 0; half < 2; half++) {
            const int row = bm0 + wm * 16 + lr + half * 8;
            float qpart = 0.0f;
            #pragma unroll
            for (int j = 0; j < 2; j++) {
                const int col = bn0 + wn * 16 + j * 8 + lc;
                const float v0 = acc[j][half * 2 + 0];
                const float v1 = acc[j][half * 2 + 1];
                const float2 xv = *(const float2*)(x + row * 256 + col);
                qpart += v0 * xv.x + v1 * xv.y;
                uint32_t ph, pl;
                split_pack(v0, v1, ph, pl);
                *(uint32_t*)(yh + row * 256 + col) = ph;
                *(uint32_t*)(yl + row * 256 + col) = pl;
            }
            qpart += __shfl_xor_sync(0xffffffffu, qpart, 1);
            qpart += __shfl_xor_sync(0xffffffffu, qpart, 2);
            if ((l & 3) == 0) atomicAdd(g_q + b * 256 + row, qpart);
        }
    } else {
        const float* qs = (const float*)(smem + QS_OFF);
        float* ob = out + ((size_t)b << 16);
        #pragma unroll
        for (int j = 0; j < 2; j++) {
            const int col = bn0 + wn * 16 + j * 8 + lc;
            const float qj0 = qs[col], qj1 = qs[col + 1];
            #pragma unroll
            for (int half = 0; half < 2; half++) {
                const int row = bm0 + wm * 16 + lr + half * 8;
                const float qi = qs[row];
                float2 v;
                v.x = qi + qj0 - 2.0f * acc[j][half * 2 + 0];
                v.y = qi + qj1 - 2.0f * acc[j][half * 2 + 1];
                *(float2*)(ob + row * 256 + col) = v;
            }
        }
    }
}

// ---------------------------------------------------------------------------
extern "C" void kernel_launch(void* const* d_in, const int* in_sizes, int n_in,
                              void* d_out, int out_size) {
    const float* x = (const float*)d_in[0];   // (256, 256) f32
    const float* M = (const float*)d_in[1];   // (16, 256, 256) f32
    float* out = (float*)d_out;               // (16, 256, 256) f32
    (void)in_sizes; (void)n_in; (void)out_size;

    (void)cudaFuncSetAttribute(k_gemm<1>, cudaFuncAttributeMaxDynamicSharedMemorySize, SMEM_B);
    (void)cudaFuncSetAttribute(k_gemm<2>, cudaFuncAttributeMaxDynamicSharedMemorySize, SMEM_B);

    k_convert<<<272, 256>>>(x, M);
    k_gemm<1><<<dim3(4, 4, 16), 512, SMEM_B>>>(x, nullptr);
    k_gemm<2><<<dim3(4, 4, 16), 512, SMEM_B>>>(x, out);
}

// round 15
// speedup vs baseline: 1.1890x; 1.1171x over previous
#include <cuda_runtime.h>
#include <cuda_bf16.h>
#include <stdint.h>

// ---------------------------------------------------------------------------
// out[b,i,j] = (x_i - x_j)^T M_b (x_i - x_j) = q_i + q_j - 2*G[b,i,j]
//   G = x M_b x^T,  q_i = G_ii.   B=16, N=D=256, fp32.
// Split-bf16 (hi/lo) mma.sync GEMMs, fp32 accum. M symmetric => no transposes.
// R15: GEMMs are byte-identical to R7 (best: 23.2us). Convert kernel now uses
//      8 floats/thread over 2x the threads (544 blocks) to fix its
//      occupancy/latency bound (was 5.7us at occ 18.6%, issue 9.8%).
// ---------------------------------------------------------------------------

__device__ __align__(16) unsigned short g_Xh[256 * 256];
__device__ __align__(16) unsigned short g_Xl[256 * 256];
__device__ __align__(16) unsigned short g_Mh[16 * 256 * 256];
__device__ __align__(16) unsigned short g_Ml[16 * 256 * 256];
__device__ __align__(16) unsigned short g_Yh[16 * 256 * 256];
__device__ __align__(16) unsigned short g_Yl[16 * 256 * 256];
__device__ float g_q[16 * 256];

__device__ __forceinline__ uint32_t smem_u32(const void* p) {
    uint32_t a;
    asm("{ .reg .u64 t; cvta.to.shared.u64 t, %1; cvt.u32.u64 %0, t; }"
        : "=r"(a) : "l"(p));
    return a;
}

__device__ __forceinline__ void cp16(uint32_t dst, const void* src) {
    asm volatile("cp.async.cg.shared.global [%0], [%1], 16;"
                 :: "r"(dst), "l"(src) : "memory");
}
#define CP_COMMIT() asm volatile("cp.async.commit_group;" ::: "memory")
template <int N>
__device__ __forceinline__ void cp_wait() {
    asm volatile("cp.async.wait_group %0;" :: "n"(N) : "memory");
}

__device__ __forceinline__ void ldm_x4(uint32_t* r, uint32_t addr) {
    asm volatile("ldmatrix.sync.aligned.m8n8.x4.shared.b16 {%0,%1,%2,%3}, [%4];"
                 : "=r"(r[0]), "=r"(r[1]), "=r"(r[2]), "=r"(r[3]) : "r"(addr));
}
__device__ __forceinline__ void mma_bf16(float* d, const uint32_t* a,
                                         uint32_t b0, uint32_t b1) {
    asm volatile(
        "mma.sync.aligned.m16n8k16.row.col.f32.bf16.bf16.f32 "
        "{%0,%1,%2,%3}, {%4,%5,%6,%7}, {%8,%9}, {%0,%1,%2,%3};"
        : "+f"(d[0]), "+f"(d[1]), "+f"(d[2]), "+f"(d[3])
        : "r"(a[0]), "r"(a[1]), "r"(a[2]), "r"(a[3]), "r"(b0), "r"(b1));
}

__device__ __forceinline__ void split_pack(float v0, float v1,
                                           uint32_t& ph, uint32_t& pl) {
    const __nv_bfloat16 h0 = __float2bfloat16(v0);
    const __nv_bfloat16 h1 = __float2bfloat16(v1);
    const __nv_bfloat16 e0 = __float2bfloat16(v0 - __bfloat162float(h0));
    const __nv_bfloat16 e1 = __float2bfloat16(v1 - __bfloat162float(h1));
    ph = (uint32_t)__bfloat16_as_ushort(h0) | ((uint32_t)__bfloat16_as_ushort(h1) << 16);
    pl = (uint32_t)__bfloat16_as_ushort(e0) | ((uint32_t)__bfloat16_as_ushort(e1) << 16);
}

// ---------------------------------------------------------------------------
// Convert: 8 consecutive floats per thread (2 independent float4 loads,
// one uint4 store per output array). 544 blocks x 256 threads covers
// M (131072 threads) + x (8192 threads). Also zeroes g_q.
// ---------------------------------------------------------------------------
__global__ void __launch_bounds__(256) k_convert(const float* __restrict__ x,
                                                 const float* __restrict__ M) {
    const int t = blockIdx.x * 256 + threadIdx.x;
    if (t < 16 * 256) g_q[t] = 0.0f;

    const float* src;
    unsigned short *dh, *dl;
    if (t < 131072) {           // M: 1,048,576 floats / 8
        src = M + (size_t)t * 8;
        dh = g_Mh + t * 8;  dl = g_Ml + t * 8;
    } else {                    // x: 65,536 floats / 8
        const int u = t - 131072;
        if (u >= 8192) return;
        src = x + (size_t)u * 8;
        dh = g_Xh + u * 8;  dl = g_Xl + u * 8;
    }

    const float4 a = ((const float4*)src)[0];
    const float4 c = ((const float4*)src)[1];
    uint32_t ph[4], pl[4];
    split_pack(a.x, a.y, ph[0], pl[0]);
    split_pack(a.z, a.w, ph[1], pl[1]);
    split_pack(c.x, c.y, ph[2], pl[2]);
    split_pack(c.z, c.w, ph[3], pl[3]);
    *(uint4*)dh = make_uint4(ph[0], ph[1], ph[2], ph[3]);
    *(uint4*)dl = make_uint4(pl[0], pl[1], pl[2], pl[3]);
}

// ---------------------------------------------------------------------------
// GEMM (identical to R7, best measured): block tile 64x64, 256 threads =
// 8 warps (2 m-warps x 4 n-warps), warp tile 32x16, BK=32, 4-stage cp.async
// pipeline.   D += Ah*Bh + Ah*Bl + Al*Bh   (fp32 register accum)
// Stage (16384B): Ah@0 (64 rows x 64B), Al@4096, Bh@8192, Bl@12288.
// 16B-chunk swizzle c ^ ((row>>1)&3) — conflict-free stores + ldmatrix.
// PHASE 1: A=x, Bt=M_b rows; epilogue -> Yh/Yl + fused partial q (atomics).
// PHASE 2: A=Y_b, Bt=x rows; epilogue -> out = q_i + q_j - 2*acc.
// ---------------------------------------------------------------------------
#define STAGES  4
#define STAGE_B 16384
#define QS_OFF  (STAGES * STAGE_B)
#define SMEM_B  (QS_OFF + 1024)

template <int PHASE>
__global__ void __launch_bounds__(256) k_gemm(const float* __restrict__ x,
                                              float* __restrict__ out) {
    extern __shared__ __align__(128) unsigned char smem[];
    const uint32_t sb = smem_u32(smem);
    const int tid = threadIdx.x;
    const int wid = tid >> 5, l = tid & 31;
    const int wm  = wid & 1, wn = wid >> 1;      // 2 x 4 warp grid
    const int b   = blockIdx.z;
    const int bm0 = blockIdx.y * 64;
    const int bn0 = blockIdx.x * 64;

    const unsigned short *Ah, *Al, *Bh, *Bl;
    if (PHASE == 1) {
        Ah = g_Xh + bm0 * 256;             Al = g_Xl + bm0 * 256;
        Bh = g_Mh + b * 65536 + bn0 * 256; Bl = g_Ml + b * 65536 + bn0 * 256;
    } else {
        Ah = g_Yh + b * 65536 + bm0 * 256; Al = g_Yl + b * 65536 + bm0 * 256;
        Bh = g_Xh + bn0 * 256;             Bl = g_Xl + bn0 * 256;
    }

    if (PHASE == 2) {
        float* qs = (float*)(smem + QS_OFF);
        qs[tid] = g_q[b * 256 + tid];
    }

    // one BK=32 chunk (kc 0..7) into stage s: 4 cp16 per thread
    auto issue = [&](int kc, int s) {
        const uint32_t st = sb + s * STAGE_B;
        const int k0 = kc * 32;
        const int row = tid >> 2;
        const int c = tid & 3;
        const uint32_t d = st + row * 64 + ((c ^ ((row >> 1) & 3)) << 4);
        const int go = row * 256 + k0 + c * 8;
        cp16(d,         Ah + go);
        cp16(d + 4096,  Al + go);
        cp16(d + 8192,  Bh + go);
        cp16(d + 12288, Bl + go);
    };

    float acc[2][2][4] = {};   // [mt][n8 j][reg]

    issue(0, 0); CP_COMMIT();
    issue(1, 1); CP_COMMIT();
    issue(2, 2); CP_COMMIT();

    const int rA = (l & 15);                    // A: row within m16 tile
    const int hA = (l >> 4);                    // A: k8-half select
    const int rB = ((l >> 4) << 3) + (l & 7);   // B: n-row within n16 group
    const int hB = ((l >> 3) & 1);              // B: k8-half select

    for (int i = 0; i < 8; i++) {
        cp_wait<2>();
        __syncthreads();
        if (i + 3 < 8) issue(i + 3, (i + 3) & 3);
        CP_COMMIT();

        const uint32_t st = sb + (i & 3) * STAGE_B;

        // hoist ALL fragments for both k-halves (12 independent ldmatrix)
        uint32_t ah[2][2][4], al[2][2][4], bh[2][4], bl[2][4];
        #pragma unroll
        for (int ks = 0; ks < 2; ks++) {
            #pragma unroll
            for (int mt = 0; mt < 2; mt++) {
                const int row = wm * 32 + mt * 16 + rA;
                const int c = (ks * 2 + hA) ^ ((row >> 1) & 3);
                const uint32_t a = st + row * 64 + (c << 4);
                ldm_x4(ah[ks][mt], a);
                ldm_x4(al[ks][mt], a + 4096);
            }
            {
                const int row = wn * 16 + rB;
                const int c = (ks * 2 + hB) ^ ((row >> 1) & 3);
                const uint32_t a = st + 8192 + row * 64 + (c << 4);
                ldm_x4(bh[ks], a);
                ldm_x4(bl[ks], a + 4096);
            }
        }
        #pragma unroll
        for (int ks = 0; ks < 2; ks++)
            #pragma unroll
            for (int mt = 0; mt < 2; mt++)
                #pragma unroll
                for (int j = 0; j < 2; j++) {
                    const int o = j * 2;
                    mma_bf16(acc[mt][j], ah[ks][mt], bh[ks][o], bh[ks][o + 1]);
                    mma_bf16(acc[mt][j], ah[ks][mt], bl[ks][o], bl[ks][o + 1]);
                    mma_bf16(acc[mt][j], al[ks][mt], bh[ks][o], bh[ks][o + 1]);
                }
    }

    // ------------------------------------------------------------------ epi
    const int lr = l >> 2;          // 0..7
    const int lc = (l & 3) * 2;     // 0,2,4,6

    if (PHASE == 1) {
        unsigned short* yh = g_Yh + b * 65536;
        unsigned short* yl = g_Yl + b * 65536;
        #pragma unroll
        for (int mt = 0; mt < 2; mt++)
            #pragma unroll
            for (int half = 0; half < 2; half++) {
                const int row = bm0 + wm * 32 + mt * 16 + lr + half * 8;
                float qpart = 0.0f;
                #pragma unroll
                for (int j = 0; j < 2; j++) {
                    const int col = bn0 + wn * 16 + j * 8 + lc;
                    const float v0 = acc[mt][j][half * 2 + 0];
                    const float v1 = acc[mt][j][half * 2 + 1];
                    const float2 xv = *(const float2*)(x + row * 256 + col);
                    qpart += v0 * xv.x + v1 * xv.y;
                    uint32_t ph, pl;
                    split_pack(v0, v1, ph, pl);
                    *(uint32_t*)(yh + row * 256 + col) = ph;
                    *(uint32_t*)(yl + row * 256 + col) = pl;
                }
                qpart += __shfl_xor_sync(0xffffffffu, qpart, 1);
                qpart += __shfl_xor_sync(0xffffffffu, qpart, 2);
                if ((l & 3) == 0) atomicAdd(g_q + b * 256 + row, qpart);
            }
    } else {
        const float* qs = (const float*)(smem + QS_OFF);
        float* ob = out + ((size_t)b << 16);
        #pragma unroll
        for (int mt = 0; mt < 2; mt++)
            #pragma unroll
            for (int j = 0; j < 2; j++) {
                const int col = bn0 + wn * 16 + j * 8 + lc;
                const float qj0 = qs[col], qj1 = qs[col + 1];
                #pragma unroll
                for (int half = 0; half < 2; half++) {
                    const int row = bm0 + wm * 32 + mt * 16 + lr + half * 8;
                    const float qi = qs[row];
                    float2 v;
                    v.x = qi + qj0 - 2.0f * acc[mt][j][half * 2 + 0];
                    v.y = qi + qj1 - 2.0f * acc[mt][j][half * 2 + 1];
                    *(float2*)(ob + row * 256 + col) = v;
                }
            }
    }
}

// ---------------------------------------------------------------------------
extern "C" void kernel_launch(void* const* d_in, const int* in_sizes, int n_in,
                              void* d_out, int out_size) {
    const float* x = (const float*)d_in[0];   // (256, 256) f32
    const float* M = (const float*)d_in[1];   // (16, 256, 256) f32
    float* out = (float*)d_out;               // (16, 256, 256) f32
    (void)in_sizes; (void)n_in; (void)out_size;

    (void)cudaFuncSetAttribute(k_gemm<1>, cudaFuncAttributeMaxDynamicSharedMemorySize, SMEM_B);
    (void)cudaFuncSetAttribute(k_gemm<2>, cudaFuncAttributeMaxDynamicSharedMemorySize, SMEM_B);

    k_convert<<<544, 256>>>(x, M);
    k_gemm<1><<<dim3(4, 4, 16), 256, SMEM_B>>>(x, nullptr);
    k_gemm<2><<<dim3(4, 4, 16), 256, SMEM_B>>>(x, out);
}